// round 16
// baseline (speedup 1.0000x reference)
#include <cuda_runtime.h>
#include <cuda_fp16.h>
#include <math.h>
#include <stdint.h>

#define NN 50000
#define N2 (2 * NN)
#define D  128
#define H2 256
#define EMAX 1000000
#define NCH 196                 // ceil(NN/256) chunks per graph

// ---------------- scratch (no allocations allowed) ----------------
// g_dego/g_degi start zero (module load) and are re-zeroed by k_offs each run.
__device__ __half g_feat16[N2 * D];
__device__ __half g_agg1[N2 * D];
__device__ __half g_m16[N2 * D];
__device__ __half g_h  [N2 * D];
__device__ float  g_ns [N2];
__device__ float  g_nd [N2];
__device__ int    g_dego[N2];
__device__ int    g_degi[N2];
__device__ int    g_off [2 * (NN + 1)];
__device__ int    g_cur [N2];
__device__ int    g_csr [2 * EMAX];
__device__ int    g_bsum[2 * NCH];
// transposed ([N,K] row-major) fp16 weights
__device__ __half g_Wt1[256 * 128];
__device__ __half g_Wt2[128 * 256];
__device__ __half g_Wt3[128 * 128];
__device__ __half g_Wt4[128 * 128];

// ---------------- helpers ----------------
__device__ __forceinline__ uint32_t smem_u32(const void* p) {
    uint32_t a;
    asm("{ .reg .u64 t; cvta.to.shared.u64 t, %1; cvt.u32.u64 %0, t; }" : "=r"(a) : "l"(p));
    return a;
}
__device__ __forceinline__ void cpasync16(uint32_t saddr, const void* gaddr, bool pred) {
    int sz = pred ? 16 : 0;
    asm volatile("cp.async.ca.shared.global [%0], [%1], 16, %2;"
                 :: "r"(saddr), "l"(gaddr), "r"(sz) : "memory");
}
__device__ __forceinline__ void cp_commit() {
    asm volatile("cp.async.commit_group;" ::: "memory");
}
__device__ __forceinline__ void mma_f16(float* c, const uint32_t* a, const uint32_t* b) {
    asm volatile(
        "mma.sync.aligned.m16n8k16.row.col.f32.f16.f16.f32 "
        "{%0,%1,%2,%3}, {%4,%5,%6,%7}, {%8,%9}, {%0,%1,%2,%3};"
        : "+f"(c[0]), "+f"(c[1]), "+f"(c[2]), "+f"(c[3])
        : "r"(a[0]), "r"(a[1]), "r"(a[2]), "r"(a[3]), "r"(b[0]), "r"(b[1]));
}
__device__ __forceinline__ void ldsm_x4(uint32_t& r0, uint32_t& r1, uint32_t& r2, uint32_t& r3,
                                        uint32_t saddr) {
    asm volatile("ldmatrix.sync.aligned.m8n8.x4.shared.b16 {%0,%1,%2,%3}, [%4];"
                 : "=r"(r0), "=r"(r1), "=r"(r2), "=r"(r3) : "r"(saddr));
}
// accumulate 8 halves (uint4) scaled by f into a[0..8)
__device__ __forceinline__ void acc8(float* a, uint4 v, float f) {
    float2 q;
    q = __half22float2(*(__half2*)&v.x); a[0] = fmaf(q.x, f, a[0]); a[1] = fmaf(q.y, f, a[1]);
    q = __half22float2(*(__half2*)&v.y); a[2] = fmaf(q.x, f, a[2]); a[3] = fmaf(q.y, f, a[3]);
    q = __half22float2(*(__half2*)&v.z); a[4] = fmaf(q.x, f, a[4]); a[5] = fmaf(q.y, f, a[5]);
    q = __half22float2(*(__half2*)&v.w); a[6] = fmaf(q.x, f, a[6]); a[7] = fmaf(q.y, f, a[7]);
}

// ------- front kernel: feat->fp16 + weight transpose + degree count -------
__global__ void k_pre(const float* __restrict__ f1, const float* __restrict__ f2,
                      const float* __restrict__ W1, const float* __restrict__ W2,
                      const float* __restrict__ W3, const float* __restrict__ W4,
                      const int* __restrict__ s1, const int* __restrict__ d1, int E1,
                      const int* __restrict__ s2, const int* __restrict__ d2, int E2) {
    int i = blockIdx.x * blockDim.x + threadIdx.x;
    if (i < N2 * (D / 4)) {
        size_t base = (size_t)i * 4;
        const float* src = (i < NN * (D / 4)) ? f1 + base : f2 + (base - (size_t)NN * D);
        float4 v = *(const float4*)src;
        __half2 h0 = __floats2half2_rn(v.x, v.y);
        __half2 h1 = __floats2half2_rn(v.z, v.w);
        uint2 st;
        st.x = *(uint32_t*)&h0;
        st.y = *(uint32_t*)&h1;
        *(uint2*)(g_feat16 + base) = st;
    }
    if (i < 128 * 256) {
        int k = i / 256, n = i % 256;
        g_Wt1[n * 128 + k] = __float2half_rn(W1[i]);
    } else if (i < 2 * 128 * 256) {
        int j = i - 128 * 256;
        int k = j / 128, n = j % 128;
        g_Wt2[n * 256 + k] = __float2half_rn(W2[j]);
    } else if (i < 2 * 128 * 256 + 128 * 128) {
        int j = i - 2 * 128 * 256;
        int k = j / 128, n = j % 128;
        g_Wt3[n * 128 + k] = __float2half_rn(W3[j]);
    } else if (i < 2 * 128 * 256 + 2 * 128 * 128) {
        int j = i - 2 * 128 * 256 - 128 * 128;
        int k = j / 128, n = j % 128;
        g_Wt4[n * 128 + k] = __float2half_rn(W4[j]);
    }
    int Etot = E1 + E2;
    if (i < Etot) {
        if (i < E1) {
            atomicAdd(&g_dego[s1[i]], 1);
            atomicAdd(&g_degi[d1[i]], 1);
        } else {
            int j = i - E1;
            atomicAdd(&g_dego[NN + s2[j]], 1);
            atomicAdd(&g_degi[NN + d2[j]], 1);
        }
    }
}

// ------ scan phase 1: norms + per-chunk degree sums ----------
__global__ void __launch_bounds__(256) k_norm_part() {
    __shared__ int ss[256];
    int blk = blockIdx.x;
    int gph = blk / NCH;
    int cb = blk - gph * NCH;
    int t = threadIdx.x;
    int i = cb * 256 + t;
    int gi = gph * NN + i;
    int d = 0;
    if (i < NN) {
        d = g_degi[gi];
        g_ns[gi] = rsqrtf(fmaxf((float)g_dego[gi], 1.f));
        g_nd[gi] = rsqrtf(fmaxf((float)d, 1.f));
    }
    ss[t] = d;
    __syncthreads();
    #pragma unroll
    for (int o = 128; o > 0; o >>= 1) {
        if (t < o) ss[t] += ss[t + o];
        __syncthreads();
    }
    if (t == 0) g_bsum[blk] = ss[0];
}

// ------ scan phase 2+3 fused: each block scans chunk sums + local scan ----
__global__ void __launch_bounds__(256) k_offs() {
    __shared__ int ss[256];
    int blk = blockIdx.x;
    int gph = blk / NCH;
    int cb = blk - gph * NCH;
    int t = threadIdx.x;

    // scan this graph's 196 chunk sums (redundant per block, cheap)
    int v = (t < NCH) ? g_bsum[gph * NCH + t] : 0;
    ss[t] = v;
    __syncthreads();
    #pragma unroll
    for (int o = 1; o < 256; o <<= 1) {
        int a = (t >= o) ? ss[t - o] : 0;
        __syncthreads();
        ss[t] += a;
        __syncthreads();
    }
    int incl = ss[t];
    if (cb == 0 && t == NCH - 1) g_off[gph * (NN + 1) + NN] = incl;
    __syncthreads();
    ss[t] = incl - v;            // exclusive prefix
    __syncthreads();
    int base = ss[cb];
    __syncthreads();

    // block-local degree scan
    int i = cb * 256 + t;
    int gi = gph * NN + i;
    int d = (i < NN) ? g_degi[gi] : 0;
    ss[t] = d;
    __syncthreads();
    #pragma unroll
    for (int o = 1; o < 256; o <<= 1) {
        int a = (t >= o) ? ss[t - o] : 0;
        __syncthreads();
        ss[t] += a;
        __syncthreads();
    }
    if (i < NN) {
        int offv = base + ss[t] - d;
        g_off[gph * (NN + 1) + i] = offv;
        g_cur[gi] = offv;
        g_degi[gi] = 0;          // ready for next invocation
        g_dego[gi] = 0;
    }
}

// ---------------- CSR fill (both graphs) ----------------
__global__ void k_fill(const int* __restrict__ s1, const int* __restrict__ d1, int E1,
                       const int* __restrict__ s2, const int* __restrict__ d2, int E2) {
    int e = blockIdx.x * blockDim.x + threadIdx.x;
    if (e < E1) {
        int p = atomicAdd(&g_cur[d1[e]], 1);
        g_csr[p] = s1[e];
    } else if (e < E1 + E2) {
        int j = e - E1;
        int p = atomicAdd(&g_cur[NN + d2[j]], 1);
        g_csr[EMAX + p] = s2[j];
    }
}

// ---- CSR gather v2: warp per node, uint4 loads, 2 rows per warp-load -----
// Lane layout: li = lane&15 covers halves [8*li, 8*li+8); sub = lane>>4 picks
// interleaved edges. Cross-half-warp combine via shfl_xor(16).
template<bool SCALE, bool POST>
__global__ void k_gather(const __half* __restrict__ X, __half* __restrict__ out,
                         const float* __restrict__ bias) {
    int w = (int)((blockIdx.x * blockDim.x + threadIdx.x) >> 5);
    if (w >= N2) return;
    int lane = threadIdx.x & 31;
    int li = lane & 15, sub = lane >> 4;
    int gph = (w >= NN) ? 1 : 0;
    int n = w - gph * NN;
    const int* off = g_off + gph * (NN + 1);
    const int* csr = g_csr + gph * EMAX;
    const float* ns = g_ns + gph * NN;
    const __half* Xg = X + (size_t)gph * NN * D + li * 8;
    int start = off[n];
    int end   = off[n + 1];

    float aA[8] = {0,0,0,0,0,0,0,0};
    float aB[8] = {0,0,0,0,0,0,0,0};
    float aC[8] = {0,0,0,0,0,0,0,0};
    float aD[8] = {0,0,0,0,0,0,0,0};

    int e = start;
    // 8 edges per iter; half-warp sub handles e+sub, e+2+sub, e+4+sub, e+6+sub
    for (; e + 7 < end; e += 8) {
        int s0 = __ldg(csr + e + sub);
        int s1 = __ldg(csr + e + 2 + sub);
        int s2 = __ldg(csr + e + 4 + sub);
        int s3 = __ldg(csr + e + 6 + sub);
        uint4 v0 = *(const uint4*)(Xg + (size_t)s0 * D);
        uint4 v1 = *(const uint4*)(Xg + (size_t)s1 * D);
        uint4 v2 = *(const uint4*)(Xg + (size_t)s2 * D);
        uint4 v3 = *(const uint4*)(Xg + (size_t)s3 * D);
        float f0 = SCALE ? __ldg(ns + s0) : 1.f;
        float f1 = SCALE ? __ldg(ns + s1) : 1.f;
        float f2 = SCALE ? __ldg(ns + s2) : 1.f;
        float f3 = SCALE ? __ldg(ns + s3) : 1.f;
        acc8(aA, v0, f0); acc8(aB, v1, f1); acc8(aC, v2, f2); acc8(aD, v3, f3);
    }
    // 2 edges per iter
    for (; e + 1 < end; e += 2) {
        int s0 = __ldg(csr + e + sub);
        uint4 v0 = *(const uint4*)(Xg + (size_t)s0 * D);
        float f0 = SCALE ? __ldg(ns + s0) : 1.f;
        acc8(aA, v0, f0);
    }
    // final single edge: half-warp 0 only
    if (e < end && sub == 0) {
        int s0 = __ldg(csr + e);
        uint4 v0 = *(const uint4*)(Xg + (size_t)s0 * D);
        float f0 = SCALE ? __ldg(ns + s0) : 1.f;
        acc8(aA, v0, f0);
    }

    float acc[8];
    #pragma unroll
    for (int i = 0; i < 8; i++) {
        acc[i] = aA[i] + aB[i] + aC[i] + aD[i];
        acc[i] += __shfl_xor_sync(0xffffffffu, acc[i], 16);
    }

    if (sub == 0) {
        if (POST) {
            float nd = g_nd[w];
            float4 b0 = *(const float4*)(bias + 8 * li);
            float4 b1 = *(const float4*)(bias + 8 * li + 4);
            acc[0] = fmaxf(fmaf(acc[0], nd, b0.x), 0.f);
            acc[1] = fmaxf(fmaf(acc[1], nd, b0.y), 0.f);
            acc[2] = fmaxf(fmaf(acc[2], nd, b0.z), 0.f);
            acc[3] = fmaxf(fmaf(acc[3], nd, b0.w), 0.f);
            acc[4] = fmaxf(fmaf(acc[4], nd, b1.x), 0.f);
            acc[5] = fmaxf(fmaf(acc[5], nd, b1.y), 0.f);
            acc[6] = fmaxf(fmaf(acc[6], nd, b1.z), 0.f);
            acc[7] = fmaxf(fmaf(acc[7], nd, b1.w), 0.f);
        }
        __half2 p0 = __floats2half2_rn(acc[0], acc[1]);
        __half2 p1 = __floats2half2_rn(acc[2], acc[3]);
        __half2 p2 = __floats2half2_rn(acc[4], acc[5]);
        __half2 p3 = __floats2half2_rn(acc[6], acc[7]);
        uint4 st;
        st.x = *(uint32_t*)&p0;
        st.y = *(uint32_t*)&p1;
        st.z = *(uint32_t*)&p2;
        st.w = *(uint32_t*)&p3;
        *(uint4*)(out + (size_t)w * D + li * 8) = st;
    }
}

// ============ fp16 mma fragment compute (256 thr, 32x64 warp tile) ========
#define LDSW 36
#define STAGE_W (128 * LDSW)

__device__ __forceinline__ void chunk_mma_h(uint32_t As_a, uint32_t Bs_a,
                                            int warp_m, int warp_n, int lane,
                                            float acc[2][8][4]) {
    uint32_t a_l = (uint32_t)(((lane & 15) * LDSW + (lane >> 4) * 4) * 4);
    uint32_t b_l = (uint32_t)((((lane >> 4) * 8 + (lane & 7)) * LDSW +
                               ((lane >> 3) & 1) * 4) * 4);
    uint32_t a_base = As_a + (uint32_t)(warp_m * 32 * LDSW * 4) + a_l;
    uint32_t b_base = Bs_a + (uint32_t)(warp_n * 64 * LDSW * 4) + b_l;

    #pragma unroll
    for (int s = 0; s < 4; s++) {
        uint32_t k0b = (uint32_t)(s * 8 * 4);
        uint32_t af[2][4];
        #pragma unroll
        for (int i = 0; i < 2; i++)
            ldsm_x4(af[i][0], af[i][1], af[i][2], af[i][3],
                    a_base + (uint32_t)(i * 16 * LDSW * 4) + k0b);
        uint32_t bf[8][2];
        #pragma unroll
        for (int t = 0; t < 4; t++)
            ldsm_x4(bf[t * 2][0], bf[t * 2][1], bf[t * 2 + 1][0], bf[t * 2 + 1][1],
                    b_base + (uint32_t)(t * 16 * LDSW * 4) + k0b);
        #pragma unroll
        for (int i = 0; i < 2; i++)
            #pragma unroll
            for (int j = 0; j < 8; j++)
                mma_f16(acc[i][j], af[i], bf[j]);
    }
}

// ====== fused encoder layer: m16 = (relu((A@W1t^T)*nd + b1)*ns) @ W2t^T ====
__global__ void __launch_bounds__(256, 2) k_layer(
    const __half* __restrict__ A, const __half* __restrict__ W1t,
    const __half* __restrict__ W2t, __half* __restrict__ Mout,
    int M, const float* __restrict__ nd, const float* __restrict__ ns,
    const float* __restrict__ b1)
{
    extern __shared__ uint32_t sm[];
    int tid = threadIdx.x;
    int lane = tid & 31, wid = tid >> 5;
    int g = lane >> 2, tig = lane & 3;
    int warp_m = wid & 3, warp_n = wid >> 2;
    int bm = blockIdx.x * 128;
    uint32_t smbase = smem_u32(sm);

    int lrow = tid >> 1;
    int lhalf = tid & 1;
    bool arv = (bm + lrow) < M;
    uint32_t sOff = (uint32_t)(lrow * LDSW + lhalf * 16) * 4;

    const __half* gA  = A   + (size_t)(arv ? bm + lrow : 0) * 128 + lhalf * 32;
    const __half* gW1 = W1t + (size_t)lrow * 128 + lhalf * 32;
    const __half* gW2 = W2t + (size_t)lrow * 256 + lhalf * 32;

    auto issue_to = [&](int stage, const __half* p, bool pred) {
        uint32_t d = smbase + (uint32_t)stage * STAGE_W * 4 + sOff;
        #pragma unroll
        for (int j = 0; j < 4; j++) cpasync16(d + j * 16, p + j * 8, pred);
        cp_commit();
    };

    float acc[2][8][4];
    #pragma unroll
    for (int i = 0; i < 2; i++)
        #pragma unroll
        for (int j = 0; j < 8; j++)
            #pragma unroll
            for (int q = 0; q < 4; q++) acc[i][j][q] = 0.f;

    int r0a = bm + warp_m * 32 + g;
    int r1a = r0a + 8;
    int r0b = r0a + 16;
    int r1b = r0b + 8;
    bool v[4] = {r0a < M, r1a < M, r0b < M, r1b < M};
    float ndv[4], nsv[4];
    ndv[0] = v[0] ? nd[r0a] : 0.f;  nsv[0] = v[0] ? ns[r0a] : 0.f;
    ndv[1] = v[1] ? nd[r1a] : 0.f;  nsv[1] = v[1] ? ns[r1a] : 0.f;
    ndv[2] = v[2] ? nd[r0b] : 0.f;  nsv[2] = v[2] ? ns[r0b] : 0.f;
    ndv[3] = v[3] ? nd[r1b] : 0.f;  nsv[3] = v[3] ? ns[r1b] : 0.f;

    auto epi_z = [&](int h) {
        #pragma unroll
        for (int i = 0; i < 2; i++) {
            int lr0 = warp_m * 32 + i * 16 + g;
            int lr1 = lr0 + 8;
            float nd0 = ndv[i * 2], ns0 = nsv[i * 2];
            float nd1 = ndv[i * 2 + 1], ns1 = nsv[i * 2 + 1];
            #pragma unroll
            for (int j = 0; j < 8; j++) {
                int cb = warp_n * 64 + j * 8 + 2 * tig;
                int gcol = h * 128 + cb;
                float2 bb = *(const float2*)(b1 + gcol);
                float o0 = fmaxf(fmaf(acc[i][j][0], nd0, bb.x), 0.f) * ns0;
                float o1 = fmaxf(fmaf(acc[i][j][1], nd0, bb.y), 0.f) * ns0;
                float o2 = fmaxf(fmaf(acc[i][j][2], nd1, bb.x), 0.f) * ns1;
                float o3 = fmaxf(fmaf(acc[i][j][3], nd1, bb.y), 0.f) * ns1;
                __half2 h0 = __floats2half2_rn(o0, o1);
                __half2 h1 = __floats2half2_rn(o2, o3);
                int cz = gcol >> 6;
                int zstage = (cz < 2) ? (4 + cz) : (cz - 2);
                int kw = (gcol & 63) >> 1;
                uint32_t* zb = sm + zstage * STAGE_W;
                zb[lr0 * LDSW + kw] = *(uint32_t*)&h0;
                zb[lr1 * LDSW + kw] = *(uint32_t*)&h1;
            }
        }
        #pragma unroll
        for (int i = 0; i < 2; i++)
            #pragma unroll
            for (int j = 0; j < 8; j++)
                #pragma unroll
                for (int q = 0; q < 4; q++) acc[i][j][q] = 0.f;
    };

    issue_to(0, gA, arv);
    issue_to(1, gA + 64, arv);
    issue_to(2, gW1, true);
    issue_to(3, gW1 + 64, true);
    asm volatile("cp.async.wait_group 0;" ::: "memory");
    __syncthreads();
    chunk_mma_h(smbase + 0 * STAGE_W * 4, smbase + 2 * STAGE_W * 4, warp_m, warp_n, lane, acc);
    chunk_mma_h(smbase + 1 * STAGE_W * 4, smbase + 3 * STAGE_W * 4, warp_m, warp_n, lane, acc);
    __syncthreads();

    issue_to(2, gW1 + 128 * 128, true);
    issue_to(3, gW1 + 128 * 128 + 64, true);
    epi_z(0);
    asm volatile("cp.async.wait_group 0;" ::: "memory");
    __syncthreads();
    chunk_mma_h(smbase + 0 * STAGE_W * 4, smbase + 2 * STAGE_W * 4, warp_m, warp_n, lane, acc);
    chunk_mma_h(smbase + 1 * STAGE_W * 4, smbase + 3 * STAGE_W * 4, warp_m, warp_n, lane, acc);
    __syncthreads();

    issue_to(2, gW2, true);
    epi_z(1);
    __syncthreads();

    const int zs[4] = {4, 5, 0, 1};
    #pragma unroll
    for (int c = 0; c < 4; c++) {
        if (c + 1 < 4) {
            issue_to(2 + ((c + 1) & 1), gW2 + (c + 1) * 64, true);
            asm volatile("cp.async.wait_group 1;" ::: "memory");
        } else {
            asm volatile("cp.async.wait_group 0;" ::: "memory");
        }
        __syncthreads();
        chunk_mma_h(smbase + (uint32_t)(zs[c] * STAGE_W * 4),
                    smbase + (uint32_t)((2 + (c & 1)) * STAGE_W * 4),
                    warp_m, warp_n, lane, acc);
        __syncthreads();
    }

    #pragma unroll
    for (int i = 0; i < 2; i++) {
        int r0 = bm + warp_m * 32 + i * 16 + g;
        int r1 = r0 + 8;
        bool v0 = v[i * 2], v1 = v[i * 2 + 1];
        #pragma unroll
        for (int j = 0; j < 8; j++) {
            int cb = warp_n * 64 + j * 8 + 2 * tig;
            __half2 h0 = __floats2half2_rn(acc[i][j][0], acc[i][j][1]);
            __half2 h1 = __floats2half2_rn(acc[i][j][2], acc[i][j][3]);
            if (v0) *(uint32_t*)(Mout + (size_t)r0 * 128 + cb) = *(uint32_t*)&h0;
            if (v1) *(uint32_t*)(Mout + (size_t)r1 * 128 + cb) = *(uint32_t*)&h1;
        }
    }
}

// ======== fused MLP: out = elu(h@W3t + b3) @ W4t + b4 (fp16 ops) ==========
__global__ void __launch_bounds__(256) k_mlp(
    const __half* __restrict__ A, const __half* __restrict__ W3t,
    const __half* __restrict__ W4t, float* __restrict__ C,
    int M, const float* __restrict__ b3, const float* __restrict__ b4)
{
    extern __shared__ uint32_t sm[];
    int tid = threadIdx.x;
    int lane = tid & 31, wid = tid >> 5;
    int g = lane >> 2, tig = lane & 3;
    int warp_m = wid & 3, warp_n = wid >> 2;
    int bm = blockIdx.x * 128;
    uint32_t smbase = smem_u32(sm);

    int lrow = tid >> 1;
    int lhalf = (tid & 1);
    bool arv = (bm + lrow) < M;
    const __half* gA  = A   + (size_t)(arv ? bm + lrow : 0) * 128 + lhalf * 32;
    const __half* gB  = W3t + (size_t)lrow * 128 + lhalf * 32;
    const __half* gW4 = W4t + (size_t)lrow * 128 + lhalf * 32;
    uint32_t sOff = (uint32_t)(lrow * LDSW + lhalf * 16) * 4;

    float acc[2][8][4];
    #pragma unroll
    for (int i = 0; i < 2; i++)
        #pragma unroll
        for (int j = 0; j < 8; j++)
            #pragma unroll
            for (int q = 0; q < 4; q++) acc[i][j][q] = 0.f;

    auto issue = [&](int c) {
        int st = c & 1;
        uint32_t da = smbase + (uint32_t)st * STAGE_W * 4 + sOff;
        uint32_t db = smbase + (uint32_t)(2 + st) * STAGE_W * 4 + sOff;
        const __half* pa = gA + c * 64;
        const __half* pb = gB + c * 64;
        #pragma unroll
        for (int j = 0; j < 4; j++) cpasync16(da + j * 16, pa + j * 8, arv);
        #pragma unroll
        for (int j = 0; j < 4; j++) cpasync16(db + j * 16, pb + j * 8, true);
        cp_commit();
    };
    auto issue_w4 = [&](int c) {
        uint32_t dw = smbase + (uint32_t)(2 + (c & 1)) * STAGE_W * 4 + sOff;
        const __half* pw = gW4 + c * 64;
        #pragma unroll
        for (int j = 0; j < 4; j++) cpasync16(dw + j * 16, pw + j * 8, true);
        cp_commit();
    };

    issue(0);
    issue(1);
    asm volatile("cp.async.wait_group 1;" ::: "memory");
    __syncthreads();
    chunk_mma_h(smbase, smbase + 2 * STAGE_W * 4, warp_m, warp_n, lane, acc);
    asm volatile("cp.async.wait_group 0;" ::: "memory");
    __syncthreads();
    chunk_mma_h(smbase + STAGE_W * 4, smbase + 3 * STAGE_W * 4, warp_m, warp_n, lane, acc);
    __syncthreads();

    issue_w4(0);
    issue_w4(1);

    #pragma unroll
    for (int i = 0; i < 2; i++) {
        int lr0 = warp_m * 32 + i * 16 + g;
        int lr1 = lr0 + 8;
        #pragma unroll
        for (int j = 0; j < 8; j++) {
            int lc = warp_n * 64 + j * 8 + 2 * tig;
            float2 bb = *(const float2*)(b3 + lc);
            float o0 = acc[i][j][0] + bb.x;
            float o1 = acc[i][j][1] + bb.y;
            float o2 = acc[i][j][2] + bb.x;
            float o3 = acc[i][j][3] + bb.y;
            o0 = (o0 > 0.f) ? o0 : expm1f(o0);
            o1 = (o1 > 0.f) ? o1 : expm1f(o1);
            o2 = (o2 > 0.f) ? o2 : expm1f(o2);
            o3 = (o3 > 0.f) ? o3 : expm1f(o3);
            __half2 h0 = __floats2half2_rn(o0, o1);
            __half2 h1 = __floats2half2_rn(o2, o3);
            int cz = lc >> 6;
            int kw = (lc & 63) >> 1;
            uint32_t* zb = sm + cz * STAGE_W;
            zb[lr0 * LDSW + kw] = *(uint32_t*)&h0;
            zb[lr1 * LDSW + kw] = *(uint32_t*)&h1;
        }
    }
    #pragma unroll
    for (int i = 0; i < 2; i++)
        #pragma unroll
        for (int j = 0; j < 8; j++)
            #pragma unroll
            for (int q = 0; q < 4; q++) acc[i][j][q] = 0.f;
    asm volatile("cp.async.wait_group 0;" ::: "memory");
    __syncthreads();

    chunk_mma_h(smbase, smbase + 2 * STAGE_W * 4, warp_m, warp_n, lane, acc);
    chunk_mma_h(smbase + STAGE_W * 4, smbase + 3 * STAGE_W * 4, warp_m, warp_n, lane, acc);

    #pragma unroll
    for (int i = 0; i < 2; i++) {
        int r0 = bm + warp_m * 32 + i * 16 + g;
        int r1 = r0 + 8;
        bool v0 = r0 < M, v1 = r1 < M;
        #pragma unroll
        for (int j = 0; j < 8; j++) {
            int cb = warp_n * 64 + j * 8 + 2 * tig;
            float2 bb = *(const float2*)(b4 + cb);
            float o0 = acc[i][j][0] + bb.x;
            float o1 = acc[i][j][1] + bb.y;
            float o2 = acc[i][j][2] + bb.x;
            float o3 = acc[i][j][3] + bb.y;
            if (v0) *(float2*)(C + (size_t)r0 * 128 + cb) = make_float2(o0, o1);
            if (v1) *(float2*)(C + (size_t)r1 * 128 + cb) = make_float2(o2, o3);
        }
    }
}

// ---------------- driver ----------------
extern "C" void kernel_launch(void* const* d_in, const int* in_sizes, int n_in,
                              void* d_out, int out_size) {
    const float* feat1 = (const float*)d_in[0];
    const float* feat2 = (const float*)d_in[1];
    const int*   ei1   = (const int*)d_in[2];
    const int*   ei2   = (const int*)d_in[3];
    const float* W1    = (const float*)d_in[4];
    const float* b1    = (const float*)d_in[5];
    const float* W2    = (const float*)d_in[6];
    const float* b2    = (const float*)d_in[7];
    const float* f1W   = (const float*)d_in[8];
    const float* f1b   = (const float*)d_in[9];
    const float* f2W   = (const float*)d_in[10];
    const float* f2b   = (const float*)d_in[11];
    int E1 = in_sizes[2] / 2;
    int E2 = in_sizes[3] / 2;
    float* out = (float*)d_out;

    __half *feat16, *agg1, *m16, *h, *wt1, *wt2, *wt3, *wt4;
    float *ns, *nd;
    cudaGetSymbolAddress((void**)&feat16, g_feat16);
    cudaGetSymbolAddress((void**)&agg1, g_agg1);
    cudaGetSymbolAddress((void**)&m16,  g_m16);
    cudaGetSymbolAddress((void**)&h,    g_h);
    cudaGetSymbolAddress((void**)&ns,   g_ns);
    cudaGetSymbolAddress((void**)&nd,   g_nd);
    cudaGetSymbolAddress((void**)&wt1,  g_Wt1);
    cudaGetSymbolAddress((void**)&wt2,  g_Wt2);
    cudaGetSymbolAddress((void**)&wt3,  g_Wt3);
    cudaGetSymbolAddress((void**)&wt4,  g_Wt4);

    const int SMEM4 = 4 * STAGE_W * 4;   // 73728
    const int SMEM6 = 6 * STAGE_W * 4;   // 110592
    cudaFuncSetAttribute(k_layer,
                         cudaFuncAttributeMaxDynamicSharedMemorySize, SMEM6);
    cudaFuncSetAttribute(k_mlp,
                         cudaFuncAttributeMaxDynamicSharedMemorySize, SMEM4);

    const int* s1 = ei1;
    const int* d1 = ei1 + E1;
    const int* s2 = ei2;
    const int* d2 = ei2 + E2;
    int Etot = E1 + E2;
    int mtiles = (N2 + 127) / 128;
    int gwarp  = (N2 * 32 + 255) / 256;

    // front-end: prep (+degree count) + CSR build (scan fused into offs)
    k_pre<<<(N2 * 32 + 255) / 256, 256>>>(feat1, feat2, W1, W2, f1W, f2W,
                                          s1, d1, E1, s2, d2, E2);
    k_norm_part<<<2 * NCH, 256>>>();
    k_offs<<<2 * NCH, 256>>>();
    k_fill<<<(Etot + 255) / 256, 256>>>(s1, d1, E1, s2, d2, E2);

    // layer 1 aggregation + fused dense layer 1+2 -> m16
    k_gather<true, false><<<gwarp, 256>>>(feat16, agg1, nullptr);
    k_layer<<<mtiles, 256, SMEM6>>>(agg1, wt1, wt2, m16, N2, nd, ns, b1);

    // layer 2 aggregation
    k_gather<false, true><<<gwarp, 256>>>(m16, h, b2);

    // fused projection MLP
    k_mlp<<<mtiles, 256, SMEM4>>>(h, wt3, wt4, out, N2, f1b, f2b);
}

// round 17
// speedup vs baseline: 1.1315x; 1.1315x over previous
#include <cuda_runtime.h>
#include <cuda_fp16.h>
#include <math.h>
#include <stdint.h>

#define NN 50000
#define N2 (2 * NN)
#define D  128
#define H2 256
#define EMAX 1000000
#define NCH 196                 // ceil(NN/256) chunks per graph

// ---------------- scratch (no allocations allowed) ----------------
// g_dego/g_degi start zero (module load) and are re-zeroed by k_offs each run.
__device__ __half g_feat16[N2 * D];
__device__ __half g_agg1[N2 * D];
__device__ __half g_m16[N2 * D];
__device__ __half g_h  [N2 * D];
__device__ float  g_ns [N2];
__device__ float  g_nd [N2];
__device__ int    g_dego[N2];
__device__ int    g_degi[N2];
__device__ int    g_off [2 * (NN + 1)];
__device__ int    g_cur [N2];
__device__ int    g_csr [2 * EMAX];
__device__ int    g_bsum[2 * NCH];
// transposed ([N,K] row-major) fp16 weights
__device__ __half g_Wt1[256 * 128];
__device__ __half g_Wt2[128 * 256];
__device__ __half g_Wt3[128 * 128];
__device__ __half g_Wt4[128 * 128];

// ---------------- helpers ----------------
__device__ __forceinline__ uint32_t smem_u32(const void* p) {
    uint32_t a;
    asm("{ .reg .u64 t; cvta.to.shared.u64 t, %1; cvt.u32.u64 %0, t; }" : "=r"(a) : "l"(p));
    return a;
}
__device__ __forceinline__ void cpasync16(uint32_t saddr, const void* gaddr, bool pred) {
    int sz = pred ? 16 : 0;
    asm volatile("cp.async.ca.shared.global [%0], [%1], 16, %2;"
                 :: "r"(saddr), "l"(gaddr), "r"(sz) : "memory");
}
__device__ __forceinline__ void cp_commit() {
    asm volatile("cp.async.commit_group;" ::: "memory");
}
__device__ __forceinline__ void mma_f16(float* c, const uint32_t* a, const uint32_t* b) {
    asm volatile(
        "mma.sync.aligned.m16n8k16.row.col.f32.f16.f16.f32 "
        "{%0,%1,%2,%3}, {%4,%5,%6,%7}, {%8,%9}, {%0,%1,%2,%3};"
        : "+f"(c[0]), "+f"(c[1]), "+f"(c[2]), "+f"(c[3])
        : "r"(a[0]), "r"(a[1]), "r"(a[2]), "r"(a[3]), "r"(b[0]), "r"(b[1]));
}
__device__ __forceinline__ void ldsm_x4(uint32_t& r0, uint32_t& r1, uint32_t& r2, uint32_t& r3,
                                        uint32_t saddr) {
    asm volatile("ldmatrix.sync.aligned.m8n8.x4.shared.b16 {%0,%1,%2,%3}, [%4];"
                 : "=r"(r0), "=r"(r1), "=r"(r2), "=r"(r3) : "r"(saddr));
}

// ------- front kernel: feat->fp16 + weight transpose + degree count -------
__global__ void k_pre(const float* __restrict__ f1, const float* __restrict__ f2,
                      const float* __restrict__ W1, const float* __restrict__ W2,
                      const float* __restrict__ W3, const float* __restrict__ W4,
                      const int* __restrict__ s1, const int* __restrict__ d1, int E1,
                      const int* __restrict__ s2, const int* __restrict__ d2, int E2) {
    int i = blockIdx.x * blockDim.x + threadIdx.x;
    if (i < N2 * (D / 4)) {
        size_t base = (size_t)i * 4;
        const float* src = (i < NN * (D / 4)) ? f1 + base : f2 + (base - (size_t)NN * D);
        float4 v = *(const float4*)src;
        __half2 h0 = __floats2half2_rn(v.x, v.y);
        __half2 h1 = __floats2half2_rn(v.z, v.w);
        uint2 st;
        st.x = *(uint32_t*)&h0;
        st.y = *(uint32_t*)&h1;
        *(uint2*)(g_feat16 + base) = st;
    }
    if (i < 128 * 256) {
        int k = i / 256, n = i % 256;
        g_Wt1[n * 128 + k] = __float2half_rn(W1[i]);
    } else if (i < 2 * 128 * 256) {
        int j = i - 128 * 256;
        int k = j / 128, n = j % 128;
        g_Wt2[n * 256 + k] = __float2half_rn(W2[j]);
    } else if (i < 2 * 128 * 256 + 128 * 128) {
        int j = i - 2 * 128 * 256;
        int k = j / 128, n = j % 128;
        g_Wt3[n * 128 + k] = __float2half_rn(W3[j]);
    } else if (i < 2 * 128 * 256 + 2 * 128 * 128) {
        int j = i - 2 * 128 * 256 - 128 * 128;
        int k = j / 128, n = j % 128;
        g_Wt4[n * 128 + k] = __float2half_rn(W4[j]);
    }
    int Etot = E1 + E2;
    if (i < Etot) {
        if (i < E1) {
            atomicAdd(&g_dego[s1[i]], 1);
            atomicAdd(&g_degi[d1[i]], 1);
        } else {
            int j = i - E1;
            atomicAdd(&g_dego[NN + s2[j]], 1);
            atomicAdd(&g_degi[NN + d2[j]], 1);
        }
    }
}

// ------ scan phase 1: norms + per-chunk degree sums ----------
__global__ void __launch_bounds__(256) k_norm_part() {
    __shared__ int ss[256];
    int blk = blockIdx.x;
    int gph = blk / NCH;
    int cb = blk - gph * NCH;
    int t = threadIdx.x;
    int i = cb * 256 + t;
    int gi = gph * NN + i;
    int d = 0;
    if (i < NN) {
        d = g_degi[gi];
        g_ns[gi] = rsqrtf(fmaxf((float)g_dego[gi], 1.f));
        g_nd[gi] = rsqrtf(fmaxf((float)d, 1.f));
    }
    ss[t] = d;
    __syncthreads();
    #pragma unroll
    for (int o = 128; o > 0; o >>= 1) {
        if (t < o) ss[t] += ss[t + o];
        __syncthreads();
    }
    if (t == 0) g_bsum[blk] = ss[0];
}

// ------ scan phase 2+3 fused: each block scans chunk sums + local scan ----
__global__ void __launch_bounds__(256) k_offs() {
    __shared__ int ss[256];
    int blk = blockIdx.x;
    int gph = blk / NCH;
    int cb = blk - gph * NCH;
    int t = threadIdx.x;

    // scan this graph's 196 chunk sums (redundant per block, cheap)
    int v = (t < NCH) ? g_bsum[gph * NCH + t] : 0;
    ss[t] = v;
    __syncthreads();
    #pragma unroll
    for (int o = 1; o < 256; o <<= 1) {
        int a = (t >= o) ? ss[t - o] : 0;
        __syncthreads();
        ss[t] += a;
        __syncthreads();
    }
    int incl = ss[t];
    if (cb == 0 && t == NCH - 1) g_off[gph * (NN + 1) + NN] = incl;
    __syncthreads();
    ss[t] = incl - v;            // exclusive prefix
    __syncthreads();
    int base = ss[cb];
    __syncthreads();

    // block-local degree scan
    int i = cb * 256 + t;
    int gi = gph * NN + i;
    int d = (i < NN) ? g_degi[gi] : 0;
    ss[t] = d;
    __syncthreads();
    #pragma unroll
    for (int o = 1; o < 256; o <<= 1) {
        int a = (t >= o) ? ss[t - o] : 0;
        __syncthreads();
        ss[t] += a;
        __syncthreads();
    }
    if (i < NN) {
        int offv = base + ss[t] - d;
        g_off[gph * (NN + 1) + i] = offv;
        g_cur[gi] = offv;
        g_degi[gi] = 0;          // ready for next invocation
        g_dego[gi] = 0;
    }
}

// ---------------- CSR fill (both graphs) ----------------
__global__ void k_fill(const int* __restrict__ s1, const int* __restrict__ d1, int E1,
                       const int* __restrict__ s2, const int* __restrict__ d2, int E2) {
    int e = blockIdx.x * blockDim.x + threadIdx.x;
    if (e < E1) {
        int p = atomicAdd(&g_cur[d1[e]], 1);
        g_csr[p] = s1[e];
    } else if (e < E1 + E2) {
        int j = e - E1;
        int p = atomicAdd(&g_cur[NN + d2[j]], 1);
        g_csr[EMAX + p] = s2[j];
    }
}

// --------- CSR gather (R15 proven): fp16 in/out, warp/node, 8-edge batch ---
template<bool SCALE, bool POST>
__global__ void k_gather(const __half* __restrict__ X, __half* __restrict__ out,
                         const float* __restrict__ bias) {
    int w = (int)((blockIdx.x * blockDim.x + threadIdx.x) >> 5);
    if (w >= N2) return;
    int lane = threadIdx.x & 31;
    int gph = (w >= NN) ? 1 : 0;
    int n = w - gph * NN;
    const int* off = g_off + gph * (NN + 1);
    const int* csr = g_csr + gph * EMAX;
    const float* ns = g_ns + gph * NN;
    const __half* Xg = X + (size_t)gph * NN * D;
    int start = off[n];
    int end   = off[n + 1];

    float4 a0 = make_float4(0.f, 0.f, 0.f, 0.f);
    float4 a1 = a0, a2 = a0, a3 = a0;

    int e = start;
    for (; e + 7 < end; e += 8) {
        int s[8];
        #pragma unroll
        for (int k = 0; k < 8; k++) s[k] = __ldg(csr + e + k);
        uint2 v[8];
        #pragma unroll
        for (int k = 0; k < 8; k++)
            v[k] = *(const uint2*)(Xg + (size_t)s[k] * D + lane * 4);
        float f[8];
        #pragma unroll
        for (int k = 0; k < 8; k++) f[k] = SCALE ? __ldg(ns + s[k]) : 1.f;
        #pragma unroll
        for (int k = 0; k < 8; k++) {
            float2 f01 = __half22float2(*(__half2*)&v[k].x);
            float2 f23 = __half22float2(*(__half2*)&v[k].y);
            float4& acc = (k & 2) ? ((k & 1) ? a3 : a2) : ((k & 1) ? a1 : a0);
            acc.x = fmaf(f01.x, f[k], acc.x);
            acc.y = fmaf(f01.y, f[k], acc.y);
            acc.z = fmaf(f23.x, f[k], acc.z);
            acc.w = fmaf(f23.y, f[k], acc.w);
        }
    }
    for (; e < end; e++) {
        int s0 = __ldg(csr + e);
        uint2 v = *(const uint2*)(Xg + (size_t)s0 * D + lane * 4);
        float2 f01 = __half22float2(*(__half2*)&v.x);
        float2 f23 = __half22float2(*(__half2*)&v.y);
        float fsc = SCALE ? __ldg(ns + s0) : 1.f;
        a0.x = fmaf(f01.x, fsc, a0.x);
        a0.y = fmaf(f01.y, fsc, a0.y);
        a0.z = fmaf(f23.x, fsc, a0.z);
        a0.w = fmaf(f23.y, fsc, a0.w);
    }
    a0.x += a1.x + a2.x + a3.x;
    a0.y += a1.y + a2.y + a3.y;
    a0.z += a1.z + a2.z + a3.z;
    a0.w += a1.w + a2.w + a3.w;

    if (POST) {
        float nd = g_nd[w];
        float4 b = *(const float4*)(bias + lane * 4);
        a0.x = fmaxf(fmaf(a0.x, nd, b.x), 0.f);
        a0.y = fmaxf(fmaf(a0.y, nd, b.y), 0.f);
        a0.z = fmaxf(fmaf(a0.z, nd, b.z), 0.f);
        a0.w = fmaxf(fmaf(a0.w, nd, b.w), 0.f);
    }
    __half2 p0 = __floats2half2_rn(a0.x, a0.y);
    __half2 p1 = __floats2half2_rn(a0.z, a0.w);
    uint2 st;
    st.x = *(uint32_t*)&p0;
    st.y = *(uint32_t*)&p1;
    *(uint2*)(out + (size_t)w * D + lane * 4) = st;
}

// ============ fp16 mma fragment compute (256 thr, 32x64 warp tile) ========
#define LDSW 36
#define STAGE_W (128 * LDSW)

__device__ __forceinline__ void chunk_mma_h(uint32_t As_a, uint32_t Bs_a,
                                            int warp_m, int warp_n, int lane,
                                            float acc[2][8][4]) {
    uint32_t a_l = (uint32_t)(((lane & 15) * LDSW + (lane >> 4) * 4) * 4);
    uint32_t b_l = (uint32_t)((((lane >> 4) * 8 + (lane & 7)) * LDSW +
                               ((lane >> 3) & 1) * 4) * 4);
    uint32_t a_base = As_a + (uint32_t)(warp_m * 32 * LDSW * 4) + a_l;
    uint32_t b_base = Bs_a + (uint32_t)(warp_n * 64 * LDSW * 4) + b_l;

    #pragma unroll
    for (int s = 0; s < 4; s++) {
        uint32_t k0b = (uint32_t)(s * 8 * 4);
        uint32_t af[2][4];
        #pragma unroll
        for (int i = 0; i < 2; i++)
            ldsm_x4(af[i][0], af[i][1], af[i][2], af[i][3],
                    a_base + (uint32_t)(i * 16 * LDSW * 4) + k0b);
        uint32_t bf[8][2];
        #pragma unroll
        for (int t = 0; t < 4; t++)
            ldsm_x4(bf[t * 2][0], bf[t * 2][1], bf[t * 2 + 1][0], bf[t * 2 + 1][1],
                    b_base + (uint32_t)(t * 16 * LDSW * 4) + k0b);
        #pragma unroll
        for (int i = 0; i < 2; i++)
            #pragma unroll
            for (int j = 0; j < 8; j++)
                mma_f16(acc[i][j], af[i], bf[j]);
    }
}

// ====== fused encoder layer: m16 = (relu((A@W1t^T)*nd + b1)*ns) @ W2t^T ====
__global__ void __launch_bounds__(256, 2) k_layer(
    const __half* __restrict__ A, const __half* __restrict__ W1t,
    const __half* __restrict__ W2t, __half* __restrict__ Mout,
    int M, const float* __restrict__ nd, const float* __restrict__ ns,
    const float* __restrict__ b1)
{
    extern __shared__ uint32_t sm[];
    int tid = threadIdx.x;
    int lane = tid & 31, wid = tid >> 5;
    int g = lane >> 2, tig = lane & 3;
    int warp_m = wid & 3, warp_n = wid >> 2;
    int bm = blockIdx.x * 128;
    uint32_t smbase = smem_u32(sm);

    int lrow = tid >> 1;
    int lhalf = tid & 1;
    bool arv = (bm + lrow) < M;
    uint32_t sOff = (uint32_t)(lrow * LDSW + lhalf * 16) * 4;

    const __half* gA  = A   + (size_t)(arv ? bm + lrow : 0) * 128 + lhalf * 32;
    const __half* gW1 = W1t + (size_t)lrow * 128 + lhalf * 32;
    const __half* gW2 = W2t + (size_t)lrow * 256 + lhalf * 32;

    auto issue_to = [&](int stage, const __half* p, bool pred) {
        uint32_t d = smbase + (uint32_t)stage * STAGE_W * 4 + sOff;
        #pragma unroll
        for (int j = 0; j < 4; j++) cpasync16(d + j * 16, p + j * 8, pred);
        cp_commit();
    };

    float acc[2][8][4];
    #pragma unroll
    for (int i = 0; i < 2; i++)
        #pragma unroll
        for (int j = 0; j < 8; j++)
            #pragma unroll
            for (int q = 0; q < 4; q++) acc[i][j][q] = 0.f;

    int r0a = bm + warp_m * 32 + g;
    int r1a = r0a + 8;
    int r0b = r0a + 16;
    int r1b = r0b + 8;
    bool v[4] = {r0a < M, r1a < M, r0b < M, r1b < M};
    float ndv[4], nsv[4];
    ndv[0] = v[0] ? nd[r0a] : 0.f;  nsv[0] = v[0] ? ns[r0a] : 0.f;
    ndv[1] = v[1] ? nd[r1a] : 0.f;  nsv[1] = v[1] ? ns[r1a] : 0.f;
    ndv[2] = v[2] ? nd[r0b] : 0.f;  nsv[2] = v[2] ? ns[r0b] : 0.f;
    ndv[3] = v[3] ? nd[r1b] : 0.f;  nsv[3] = v[3] ? ns[r1b] : 0.f;

    auto epi_z = [&](int h) {
        #pragma unroll
        for (int i = 0; i < 2; i++) {
            int lr0 = warp_m * 32 + i * 16 + g;
            int lr1 = lr0 + 8;
            float nd0 = ndv[i * 2], ns0 = nsv[i * 2];
            float nd1 = ndv[i * 2 + 1], ns1 = nsv[i * 2 + 1];
            #pragma unroll
            for (int j = 0; j < 8; j++) {
                int cb = warp_n * 64 + j * 8 + 2 * tig;
                int gcol = h * 128 + cb;
                float2 bb = *(const float2*)(b1 + gcol);
                float o0 = fmaxf(fmaf(acc[i][j][0], nd0, bb.x), 0.f) * ns0;
                float o1 = fmaxf(fmaf(acc[i][j][1], nd0, bb.y), 0.f) * ns0;
                float o2 = fmaxf(fmaf(acc[i][j][2], nd1, bb.x), 0.f) * ns1;
                float o3 = fmaxf(fmaf(acc[i][j][3], nd1, bb.y), 0.f) * ns1;
                __half2 h0 = __floats2half2_rn(o0, o1);
                __half2 h1 = __floats2half2_rn(o2, o3);
                int cz = gcol >> 6;
                int zstage = (cz < 2) ? (4 + cz) : (cz - 2);
                int kw = (gcol & 63) >> 1;
                uint32_t* zb = sm + zstage * STAGE_W;
                zb[lr0 * LDSW + kw] = *(uint32_t*)&h0;
                zb[lr1 * LDSW + kw] = *(uint32_t*)&h1;
            }
        }
        #pragma unroll
        for (int i = 0; i < 2; i++)
            #pragma unroll
            for (int j = 0; j < 8; j++)
                #pragma unroll
                for (int q = 0; q < 4; q++) acc[i][j][q] = 0.f;
    };

    issue_to(0, gA, arv);
    issue_to(1, gA + 64, arv);
    issue_to(2, gW1, true);
    issue_to(3, gW1 + 64, true);
    asm volatile("cp.async.wait_group 0;" ::: "memory");
    __syncthreads();
    chunk_mma_h(smbase + 0 * STAGE_W * 4, smbase + 2 * STAGE_W * 4, warp_m, warp_n, lane, acc);
    chunk_mma_h(smbase + 1 * STAGE_W * 4, smbase + 3 * STAGE_W * 4, warp_m, warp_n, lane, acc);
    __syncthreads();

    issue_to(2, gW1 + 128 * 128, true);
    issue_to(3, gW1 + 128 * 128 + 64, true);
    epi_z(0);
    asm volatile("cp.async.wait_group 0;" ::: "memory");
    __syncthreads();
    chunk_mma_h(smbase + 0 * STAGE_W * 4, smbase + 2 * STAGE_W * 4, warp_m, warp_n, lane, acc);
    chunk_mma_h(smbase + 1 * STAGE_W * 4, smbase + 3 * STAGE_W * 4, warp_m, warp_n, lane, acc);
    __syncthreads();

    issue_to(2, gW2, true);
    epi_z(1);
    __syncthreads();

    const int zs[4] = {4, 5, 0, 1};
    #pragma unroll
    for (int c = 0; c < 4; c++) {
        if (c + 1 < 4) {
            issue_to(2 + ((c + 1) & 1), gW2 + (c + 1) * 64, true);
            asm volatile("cp.async.wait_group 1;" ::: "memory");
        } else {
            asm volatile("cp.async.wait_group 0;" ::: "memory");
        }
        __syncthreads();
        chunk_mma_h(smbase + (uint32_t)(zs[c] * STAGE_W * 4),
                    smbase + (uint32_t)((2 + (c & 1)) * STAGE_W * 4),
                    warp_m, warp_n, lane, acc);
        __syncthreads();
    }

    #pragma unroll
    for (int i = 0; i < 2; i++) {
        int r0 = bm + warp_m * 32 + i * 16 + g;
        int r1 = r0 + 8;
        bool v0 = v[i * 2], v1 = v[i * 2 + 1];
        #pragma unroll
        for (int j = 0; j < 8; j++) {
            int cb = warp_n * 64 + j * 8 + 2 * tig;
            __half2 h0 = __floats2half2_rn(acc[i][j][0], acc[i][j][1]);
            __half2 h1 = __floats2half2_rn(acc[i][j][2], acc[i][j][3]);
            if (v0) *(uint32_t*)(Mout + (size_t)r0 * 128 + cb) = *(uint32_t*)&h0;
            if (v1) *(uint32_t*)(Mout + (size_t)r1 * 128 + cb) = *(uint32_t*)&h1;
        }
    }
}

// ======== fused MLP: out = elu(h@W3t + b3) @ W4t + b4 (fp16 ops) ==========
__global__ void __launch_bounds__(256) k_mlp(
    const __half* __restrict__ A, const __half* __restrict__ W3t,
    const __half* __restrict__ W4t, float* __restrict__ C,
    int M, const float* __restrict__ b3, const float* __restrict__ b4)
{
    extern __shared__ uint32_t sm[];
    int tid = threadIdx.x;
    int lane = tid & 31, wid = tid >> 5;
    int g = lane >> 2, tig = lane & 3;
    int warp_m = wid & 3, warp_n = wid >> 2;
    int bm = blockIdx.x * 128;
    uint32_t smbase = smem_u32(sm);

    int lrow = tid >> 1;
    int lhalf = (tid & 1);
    bool arv = (bm + lrow) < M;
    const __half* gA  = A   + (size_t)(arv ? bm + lrow : 0) * 128 + lhalf * 32;
    const __half* gB  = W3t + (size_t)lrow * 128 + lhalf * 32;
    const __half* gW4 = W4t + (size_t)lrow * 128 + lhalf * 32;
    uint32_t sOff = (uint32_t)(lrow * LDSW + lhalf * 16) * 4;

    float acc[2][8][4];
    #pragma unroll
    for (int i = 0; i < 2; i++)
        #pragma unroll
        for (int j = 0; j < 8; j++)
            #pragma unroll
            for (int q = 0; q < 4; q++) acc[i][j][q] = 0.f;

    auto issue = [&](int c) {
        int st = c & 1;
        uint32_t da = smbase + (uint32_t)st * STAGE_W * 4 + sOff;
        uint32_t db = smbase + (uint32_t)(2 + st) * STAGE_W * 4 + sOff;
        const __half* pa = gA + c * 64;
        const __half* pb = gB + c * 64;
        #pragma unroll
        for (int j = 0; j < 4; j++) cpasync16(da + j * 16, pa + j * 8, arv);
        #pragma unroll
        for (int j = 0; j < 4; j++) cpasync16(db + j * 16, pb + j * 8, true);
        cp_commit();
    };
    auto issue_w4 = [&](int c) {
        uint32_t dw = smbase + (uint32_t)(2 + (c & 1)) * STAGE_W * 4 + sOff;
        const __half* pw = gW4 + c * 64;
        #pragma unroll
        for (int j = 0; j < 4; j++) cpasync16(dw + j * 16, pw + j * 8, true);
        cp_commit();
    };

    issue(0);
    issue(1);
    asm volatile("cp.async.wait_group 1;" ::: "memory");
    __syncthreads();
    chunk_mma_h(smbase, smbase + 2 * STAGE_W * 4, warp_m, warp_n, lane, acc);
    asm volatile("cp.async.wait_group 0;" ::: "memory");
    __syncthreads();
    chunk_mma_h(smbase + STAGE_W * 4, smbase + 3 * STAGE_W * 4, warp_m, warp_n, lane, acc);
    __syncthreads();

    issue_w4(0);
    issue_w4(1);

    #pragma unroll
    for (int i = 0; i < 2; i++) {
        int lr0 = warp_m * 32 + i * 16 + g;
        int lr1 = lr0 + 8;
        #pragma unroll
        for (int j = 0; j < 8; j++) {
            int lc = warp_n * 64 + j * 8 + 2 * tig;
            float2 bb = *(const float2*)(b3 + lc);
            float o0 = acc[i][j][0] + bb.x;
            float o1 = acc[i][j][1] + bb.y;
            float o2 = acc[i][j][2] + bb.x;
            float o3 = acc[i][j][3] + bb.y;
            o0 = (o0 > 0.f) ? o0 : expm1f(o0);
            o1 = (o1 > 0.f) ? o1 : expm1f(o1);
            o2 = (o2 > 0.f) ? o2 : expm1f(o2);
            o3 = (o3 > 0.f) ? o3 : expm1f(o3);
            __half2 h0 = __floats2half2_rn(o0, o1);
            __half2 h1 = __floats2half2_rn(o2, o3);
            int cz = lc >> 6;
            int kw = (lc & 63) >> 1;
            uint32_t* zb = sm + cz * STAGE_W;
            zb[lr0 * LDSW + kw] = *(uint32_t*)&h0;
            zb[lr1 * LDSW + kw] = *(uint32_t*)&h1;
        }
    }
    #pragma unroll
    for (int i = 0; i < 2; i++)
        #pragma unroll
        for (int j = 0; j < 8; j++)
            #pragma unroll
            for (int q = 0; q < 4; q++) acc[i][j][q] = 0.f;
    asm volatile("cp.async.wait_group 0;" ::: "memory");
    __syncthreads();

    chunk_mma_h(smbase, smbase + 2 * STAGE_W * 4, warp_m, warp_n, lane, acc);
    chunk_mma_h(smbase + STAGE_W * 4, smbase + 3 * STAGE_W * 4, warp_m, warp_n, lane, acc);

    #pragma unroll
    for (int i = 0; i < 2; i++) {
        int r0 = bm + warp_m * 32 + i * 16 + g;
        int r1 = r0 + 8;
        bool v0 = r0 < M, v1 = r1 < M;
        #pragma unroll
        for (int j = 0; j < 8; j++) {
            int cb = warp_n * 64 + j * 8 + 2 * tig;
            float2 bb = *(const float2*)(b4 + cb);
            float o0 = acc[i][j][0] + bb.x;
            float o1 = acc[i][j][1] + bb.y;
            float o2 = acc[i][j][2] + bb.x;
            float o3 = acc[i][j][3] + bb.y;
            if (v0) *(float2*)(C + (size_t)r0 * 128 + cb) = make_float2(o0, o1);
            if (v1) *(float2*)(C + (size_t)r1 * 128 + cb) = make_float2(o2, o3);
        }
    }
}

// ---------------- driver ----------------
extern "C" void kernel_launch(void* const* d_in, const int* in_sizes, int n_in,
                              void* d_out, int out_size) {
    const float* feat1 = (const float*)d_in[0];
    const float* feat2 = (const float*)d_in[1];
    const int*   ei1   = (const int*)d_in[2];
    const int*   ei2   = (const int*)d_in[3];
    const float* W1    = (const float*)d_in[4];
    const float* b1    = (const float*)d_in[5];
    const float* W2    = (const float*)d_in[6];
    const float* b2    = (const float*)d_in[7];
    const float* f1W   = (const float*)d_in[8];
    const float* f1b   = (const float*)d_in[9];
    const float* f2W   = (const float*)d_in[10];
    const float* f2b   = (const float*)d_in[11];
    int E1 = in_sizes[2] / 2;
    int E2 = in_sizes[3] / 2;
    float* out = (float*)d_out;

    __half *feat16, *agg1, *m16, *h, *wt1, *wt2, *wt3, *wt4;
    float *ns, *nd;
    cudaGetSymbolAddress((void**)&feat16, g_feat16);
    cudaGetSymbolAddress((void**)&agg1, g_agg1);
    cudaGetSymbolAddress((void**)&m16,  g_m16);
    cudaGetSymbolAddress((void**)&h,    g_h);
    cudaGetSymbolAddress((void**)&ns,   g_ns);
    cudaGetSymbolAddress((void**)&nd,   g_nd);
    cudaGetSymbolAddress((void**)&wt1,  g_Wt1);
    cudaGetSymbolAddress((void**)&wt2,  g_Wt2);
    cudaGetSymbolAddress((void**)&wt3,  g_Wt3);
    cudaGetSymbolAddress((void**)&wt4,  g_Wt4);

    const int SMEM4 = 4 * STAGE_W * 4;   // 73728
    const int SMEM6 = 6 * STAGE_W * 4;   // 110592
    cudaFuncSetAttribute(k_layer,
                         cudaFuncAttributeMaxDynamicSharedMemorySize, SMEM6);
    cudaFuncSetAttribute(k_mlp,
                         cudaFuncAttributeMaxDynamicSharedMemorySize, SMEM4);

    const int* s1 = ei1;
    const int* d1 = ei1 + E1;
    const int* s2 = ei2;
    const int* d2 = ei2 + E2;
    int Etot = E1 + E2;
    int mtiles = (N2 + 127) / 128;
    int gwarp  = (N2 * 32 + 255) / 256;

    // front-end: prep (+degree count) + CSR build (scan fused into offs)
    k_pre<<<(N2 * 32 + 255) / 256, 256>>>(feat1, feat2, W1, W2, f1W, f2W,
                                          s1, d1, E1, s2, d2, E2);
    k_norm_part<<<2 * NCH, 256>>>();
    k_offs<<<2 * NCH, 256>>>();
    k_fill<<<(Etot + 255) / 256, 256>>>(s1, d1, E1, s2, d2, E2);

    // layer 1 aggregation + fused dense layer 1+2 -> m16
    k_gather<true, false><<<gwarp, 256>>>(feat16, agg1, nullptr);
    k_layer<<<mtiles, 256, SMEM6>>>(agg1, wt1, wt2, m16, N2, nd, ns, b1);

    // layer 2 aggregation
    k_gather<false, true><<<gwarp, 256>>>(m16, h, b2);

    // fused projection MLP
    k_mlp<<<mtiles, 256, SMEM4>>>(h, wt3, wt4, out, N2, f1b, f2b);
}